// round 4
// baseline (speedup 1.0000x reference)
#include <cuda_runtime.h>
#include <math.h>

#define D_IN   768
#define TWO_D  1536
#define Q_N    128
#define S_N    512
#define C_N    64
#define M_ALL  (Q_N + S_N)          /* 640 combined GEMM rows */
#define JCHUNKS 8
#define JPER   (TWO_D / JCHUNKS)    /* 192 */

// Scratch (device globals: allocation-free per harness rules)
__device__ float  v4_hq[Q_N * TWO_D];             // hq (+b1)  [128,1536]
__device__ float  v4_hs[S_N * TWO_D];             // hs        [512,1536]
__device__ double v4_part[JCHUNKS * Q_N * S_N];   // fp64 partial scores per j-chunk
__device__ double v4_loss[Q_N];                   // per-query -logp

// fp32 -> tf32 (10-bit mantissa, round-to-nearest-away): the conversion the
// tensor-core HW / cuBLAS TF32 path applies to fp32 GEMM inputs. Emulates the
// reference's (JAX default GPU matmul) input quantization.
__device__ __forceinline__ float v4_tf32(float x) {
    unsigned u;
    asm("cvt.rna.tf32.f32 %0, %1;" : "=r"(u) : "f"(x));
    return __uint_as_float(u);
}

// ---------------------------------------------------------------------------
// Combined TF32-emulated GEMM (NT), both hq and hs in one launch.
// Rows [0,128)   : hq[m][j] = sum_d tf32(query[m][d])   * tf32(W1[j][d])     + b1[j]
// Rows [128,640) : hs[m][j] = sum_d tf32(support[m][d]) * tf32(W1[j][768+d])
// BM=64, BN=64, BK=16, 256 threads, 4x4/thread, fp64 flush every 64 k.
// grid = (TWO_D/64 = 24, M_ALL/64 = 10)
// ---------------------------------------------------------------------------
__global__ void v4_gemm(const float* __restrict__ query,
                        const float* __restrict__ support,
                        const float* __restrict__ W1,
                        const float* __restrict__ b1)
{
    __shared__ __align__(16) float As[16][68];
    __shared__ __align__(16) float Bs[16][68];

    const int tid   = threadIdx.x;
    const int mBase = blockIdx.y * 64;
    const int jBase = blockIdx.x * 64;
    const bool isQ  = (blockIdx.y < 2);

    const float* Abase = isQ ? query : support;
    const int rowOff   = isQ ? mBase : (mBase - Q_N);
    const int wOff     = isQ ? 0 : D_IN;
    float* Cbase = isQ ? (v4_hq + (size_t)mBase * TWO_D)
                       : (v4_hs + (size_t)(mBase - Q_N) * TWO_D);

    const int ty = tid >> 4;      // 0..15 (m micro)
    const int tx = tid & 15;      // 0..15 (n micro)
    const int lr = tid >> 2;      // 0..63 tile row for loads
    const int lc = tid & 3;       // 0..3 float4 slot along k

    const float* aPtr = Abase + (size_t)(rowOff + lr) * D_IN + lc * 4;
    const float* bPtr = W1 + (size_t)(jBase + lr) * TWO_D + wOff + lc * 4;

    double dacc[4][4] = {};
    float  part[4][4] = {};

    for (int kt = 0; kt < D_IN; kt += 16) {
        float4 av = *(const float4*)(aPtr + kt);
        float4 bv = *(const float4*)(bPtr + kt);
        __syncthreads();
        As[lc*4+0][lr] = v4_tf32(av.x); As[lc*4+1][lr] = v4_tf32(av.y);
        As[lc*4+2][lr] = v4_tf32(av.z); As[lc*4+3][lr] = v4_tf32(av.w);
        Bs[lc*4+0][lr] = v4_tf32(bv.x); Bs[lc*4+1][lr] = v4_tf32(bv.y);
        Bs[lc*4+2][lr] = v4_tf32(bv.z); Bs[lc*4+3][lr] = v4_tf32(bv.w);
        __syncthreads();
        #pragma unroll
        for (int k = 0; k < 16; k++) {
            float4 a4 = *(const float4*)&As[k][ty*4];
            float4 b4 = *(const float4*)&Bs[k][tx*4];
            float a[4] = {a4.x, a4.y, a4.z, a4.w};
            float b[4] = {b4.x, b4.y, b4.z, b4.w};
            #pragma unroll
            for (int i = 0; i < 4; i++)
                #pragma unroll
                for (int j = 0; j < 4; j++)
                    part[i][j] = fmaf(a[i], b[j], part[i][j]);
        }
        if (((kt >> 4) & 3) == 3) {            // fp64 flush every 64 k
            #pragma unroll
            for (int i = 0; i < 4; i++)
                #pragma unroll
                for (int j = 0; j < 4; j++) {
                    dacc[i][j] += (double)part[i][j];
                    part[i][j] = 0.0f;
                }
        }
    }

    #pragma unroll
    for (int i = 0; i < 4; i++) {
        const int lm = ty*4 + i;
        #pragma unroll
        for (int j = 0; j < 4; j++) {
            const int jj = jBase + tx*4 + j;
            float v = (float)dacc[i][j];
            if (isQ) v += b1[jj];
            Cbase[(size_t)lm * TWO_D + jj] = v;
        }
    }
}

// ---------------------------------------------------------------------------
// Scores partial (fp64): part[z][q][s] = sum_{j in chunk z} relu(hq[q][j]+hs[s][j])*w2[j]
// Exact fp32 inner per 16-j tile, fp64 flush each tile.
// Tile QT=32, ST=64, JT=16. 256 threads, 2x4/thread.
// grid = (S/64=8, Q/32=4, JCHUNKS=8) = 256 blocks
// ---------------------------------------------------------------------------
__global__ void v4_scores(const float* __restrict__ W2)
{
    __shared__ __align__(16) float Aq[16][36];
    __shared__ __align__(16) float Bs[16][68];
    __shared__ float ws[16];

    const int tid    = threadIdx.x;
    const int sBase  = blockIdx.x * 64;
    const int qBase  = blockIdx.y * 32;
    const int jcBase = blockIdx.z * JPER;
    const int ty = tid >> 4;      // 0..15 (q micro: 2 rows)
    const int tx = tid & 15;      // 0..15 (s micro: 4 cols)

    const int aq_q = tid >> 3;           // 0..31
    const int aq_j = (tid & 7) * 2;      // 0..14
    const float* hqPtr = v4_hq + (size_t)(qBase + aq_q) * TWO_D + jcBase + aq_j;
    const int bs_s = tid >> 2;           // 0..63
    const int bs_j = (tid & 3) * 4;      // 0..12
    const float* hsPtr = v4_hs + (size_t)(sBase + bs_s) * TWO_D + jcBase + bs_j;

    double dacc[2][4] = {};

    for (int jt = 0; jt < JPER; jt += 16) {
        float2 a2 = *(const float2*)(hqPtr + jt);
        float4 b4 = *(const float4*)(hsPtr + jt);
        float wv = (tid < 16) ? W2[jcBase + jt + tid] : 0.0f;
        __syncthreads();
        Aq[aq_j+0][aq_q] = a2.x;
        Aq[aq_j+1][aq_q] = a2.y;
        Bs[bs_j+0][bs_s] = b4.x; Bs[bs_j+1][bs_s] = b4.y;
        Bs[bs_j+2][bs_s] = b4.z; Bs[bs_j+3][bs_s] = b4.w;
        if (tid < 16) ws[tid] = wv;
        __syncthreads();

        float p[2][4] = {};
        #pragma unroll
        for (int k = 0; k < 16; k++) {
            const float w  = ws[k];
            float2 aa = *(const float2*)&Aq[k][ty*2];
            float4 bb = *(const float4*)&Bs[k][tx*4];
            float a[2] = {aa.x, aa.y};
            float b[4] = {bb.x, bb.y, bb.z, bb.w};
            #pragma unroll
            for (int i = 0; i < 2; i++)
                #pragma unroll
                for (int l = 0; l < 4; l++) {
                    float t = a[i] + b[l];       // single fp32 rounding (matches ref)
                    t = fmaxf(t, 0.0f);
                    p[i][l] = fmaf(t, w, p[i][l]);
                }
        }
        #pragma unroll
        for (int i = 0; i < 2; i++)
            #pragma unroll
            for (int l = 0; l < 4; l++)
                dacc[i][l] += (double)p[i][l];
    }

    double* outp = v4_part + (size_t)blockIdx.z * (Q_N * S_N);
    #pragma unroll
    for (int i = 0; i < 2; i++)
        #pragma unroll
        for (int l = 0; l < 4; l++)
            outp[(size_t)(qBase + ty*2 + i) * S_N + sBase + tx*4 + l] = dacc[i][l];
}

// ---------------------------------------------------------------------------
// Per-query aggregate + softmax + pred. grid = 128 blocks (1/query), 128 thr.
// All fp64, deterministic fixed-order reductions.
// out[1+q] = (argmax == target), v4_loss[q] = -logp
// ---------------------------------------------------------------------------
__global__ void v4_agg(const int* __restrict__ labels,
                       const int* __restrict__ targets,
                       const float* __restrict__ b2,
                       float* __restrict__ out, int out_size)
{
    __shared__ double sc[S_N];
    __shared__ int    lab[S_N];
    __shared__ double aggv[C_N];
    __shared__ double redv[C_N];
    __shared__ int    redi[C_N];
    __shared__ double rede[C_N];

    const int q   = blockIdx.x;
    const int tid = threadIdx.x;
    const double b2v = (double)b2[0];

    for (int s = tid; s < S_N; s += 128) lab[s] = labels[s];

    // scores[s] = sum over 8 fp64 chunk partials + b2 (fixed order)
    for (int s = tid; s < S_N; s += 128) {
        double v = 0.0;
        #pragma unroll
        for (int z = 0; z < JCHUNKS; z++)
            v += v4_part[(size_t)z * (Q_N * S_N) + (size_t)q * S_N + s];
        sc[s] = v + b2v;
    }
    __syncthreads();

    // per-class mean (labels sorted; thread c scans sequentially -> deterministic)
    if (tid < C_N) {
        double ssum = 0.0;
        int cnt = 0;
        for (int s = 0; s < S_N; s++)
            if (lab[s] == tid) { ssum += sc[s]; cnt++; }
        aggv[tid] = ssum / (double)(cnt > 1 ? cnt : 1);
        redv[tid] = aggv[tid];
        redi[tid] = tid;
    }
    __syncthreads();

    // argmax reduce, first-index-on-ties (strict > takes the higher half)
    #pragma unroll
    for (int off = C_N / 2; off > 0; off >>= 1) {
        if (tid < off) {
            if (redv[tid + off] > redv[tid] ||
                (redv[tid + off] == redv[tid] && redi[tid + off] < redi[tid])) {
                redv[tid] = redv[tid + off];
                redi[tid] = redi[tid + off];
            }
        }
        __syncthreads();
    }
    const double mx = redv[0];
    const int    am = redi[0];

    if (tid < C_N) rede[tid] = exp(aggv[tid] - mx);
    __syncthreads();
    #pragma unroll
    for (int off = C_N / 2; off > 0; off >>= 1) {
        if (tid < off) rede[tid] += rede[tid + off];
        __syncthreads();
    }

    if (tid == 0) {
        const int tgt = targets[q];
        const double logp = aggv[tgt] - mx - log(rede[0]);
        v4_loss[q] = -logp;
        if (1 + q < out_size) out[1 + q] = (am == tgt) ? 1.0f : 0.0f;
    }
}

// ---------------------------------------------------------------------------
// Final loss mean. 1 block, 128 threads.
// ---------------------------------------------------------------------------
__global__ void v4_final(float* __restrict__ out, int out_size)
{
    __shared__ double red[Q_N];
    const int tid = threadIdx.x;
    red[tid] = v4_loss[tid];
    __syncthreads();
    #pragma unroll
    for (int off = Q_N / 2; off > 0; off >>= 1) {
        if (tid < off) red[tid] += red[tid + off];
        __syncthreads();
    }
    if (tid == 0 && out_size > 0) out[0] = (float)(red[0] / (double)Q_N);
}

// ---------------------------------------------------------------------------
extern "C" void kernel_launch(void* const* d_in, const int* in_sizes, int n_in,
                              void* d_out, int out_size)
{
    const float* query   = (const float*)d_in[0];   // [128,768]
    const float* support = (const float*)d_in[1];   // [512,768]
    const float* W1      = (const float*)d_in[2];   // [1536,1536]
    const float* b1      = (const float*)d_in[3];   // [1536]
    const float* W2      = (const float*)d_in[4];   // [1,1536]
    const float* b2      = (const float*)d_in[5];   // [1]
    const int*   labels  = (const int*)  d_in[6];   // [512] sorted
    const int*   targets = (const int*)  d_in[7];   // [128]
    (void)in_sizes; (void)n_in;

    float* out = (float*)d_out;

    v4_gemm  <<<dim3(TWO_D/64, M_ALL/64), 256>>>(query, support, W1, b1);
    v4_scores<<<dim3(S_N/64, Q_N/32, JCHUNKS), 256>>>(W2);
    v4_agg   <<<Q_N, 128>>>(labels, targets, b2, out, out_size);
    v4_final <<<1, Q_N>>>(out, out_size);
}

// round 6
// speedup vs baseline: 1.8388x; 1.8388x over previous
#include <cuda_runtime.h>
#include <math.h>
#include <stdint.h>

#define D_IN   768
#define TWO_D  1536
#define Q_N    128
#define S_N    512
#define C_N    64
#define JCHUNKS 8
#define JPER   (TWO_D / JCHUNKS)    /* 192 */

// Scratch (device globals: allocation-free per harness rules)
__device__ float  v6_hq[Q_N * TWO_D];             // hq (+b1)  [128,1536]
__device__ float  v6_hs[S_N * TWO_D];             // hs        [512,1536]
__device__ double v6_part[JCHUNKS * Q_N * S_N];   // fp64 partial scores per j-chunk
__device__ double v6_loss[Q_N];                   // per-query -logp

// fp32 -> tf32 RNA rounding (matches cuBLAS TF32 input quantization = reference)
__device__ __forceinline__ float v6_tf32(float x) {
    unsigned u;
    asm("cvt.rna.tf32.f32 %0, %1;" : "=r"(u) : "f"(x));
    return __uint_as_float(u);
}

// m16n8k8 tf32 mma (base ISA, sm_80+; compiles for compute_103)
__device__ __forceinline__ void v6_mma(float d[4], const unsigned a[4], const unsigned b[2]) {
    asm volatile(
        "mma.sync.aligned.m16n8k8.row.col.f32.tf32.tf32.f32 "
        "{%0,%1,%2,%3}, {%4,%5,%6,%7}, {%8,%9}, {%0,%1,%2,%3};"
        : "+f"(d[0]), "+f"(d[1]), "+f"(d[2]), "+f"(d[3])
        : "r"(a[0]), "r"(a[1]), "r"(a[2]), "r"(a[3]), "r"(b[0]), "r"(b[1]));
}

// ---------------------------------------------------------------------------
// TF32 tensor-core GEMM: h[m][j] = sum_d tf32(A[m][d]) * tf32(W1[j][wOff+d])
// CTA 64m x 128n, K=768 in 24 double-buffered k-tiles of 32.
// SMEM layout: stride 40 floats/row; within each 8-col k-group, columns stored
// as interleaved pairs (c, c+4) so each mma fragment is one lds.64,
// conflict-free (bank = 8*g + 2*t distinct per 16-lane wavefront).
// 256 threads = 8 warps (2M x 4N), warp tile 32x32.
// grid = (TWO_D/128 = 12, M_tiles = 10: y<2 query, y>=2 support)
// ---------------------------------------------------------------------------
#define V6_ST     40
#define V6_ASZ    (2 * 64 * V6_ST)            /* floats */
#define V6_BSZ    (2 * 128 * V6_ST)
#define V6_SMEM   ((V6_ASZ + V6_BSZ) * 4)     /* 61440 bytes */

__global__ void __launch_bounds__(256, 1)
v6_gemm(const float* __restrict__ query,
        const float* __restrict__ support,
        const float* __restrict__ W1,
        const float* __restrict__ b1)
{
    extern __shared__ __align__(16) float smem[];
    float* As = smem;              // [2][64][40]
    float* Bs = smem + V6_ASZ;     // [2][128][40]

    const int tid  = threadIdx.x;
    const int lane = tid & 31;
    const int wid  = tid >> 5;
    const int warpM = wid & 1;          // 0..1
    const int warpN = wid >> 1;         // 0..3
    const int g = lane >> 2;            // 0..7
    const int t = lane & 3;             // 0..3

    const bool isQ  = (blockIdx.y < 2);
    const float* Arow = isQ ? (query + (size_t)blockIdx.y * 64 * D_IN)
                            : (support + (size_t)(blockIdx.y - 2) * 64 * D_IN);
    const int   wOff  = isQ ? 0 : D_IN;
    const int   jBase = blockIdx.x * 128;
    float* Crow = isQ ? (v6_hq + (size_t)blockIdx.y * 64 * TWO_D)
                      : (v6_hs + (size_t)(blockIdx.y - 2) * 64 * TWO_D);

    // staging assignments (8 consecutive k per segment)
    const int a_row = tid >> 2, a_ks = tid & 3;                 // 1 A segment
    const int b_row0 = tid >> 2, b_ks0 = tid & 3;               // 2 B segments
    const int b_row1 = (tid + 256) >> 2, b_ks1 = tid & 3;
    const float* aSeg  = Arow + (size_t)a_row * D_IN + a_ks * 8;
    const float* bSeg0 = W1 + (size_t)(jBase + b_row0) * TWO_D + wOff + b_ks0 * 8;
    const float* bSeg1 = W1 + (size_t)(jBase + b_row1) * TWO_D + wOff + b_ks1 * 8;

    float4 pa0, pa1, pb00, pb01, pb10, pb11;
    #define V6_PREFETCH(kb) do {                                   \
        pa0  = *(const float4*)(aSeg  + (kb));                     \
        pa1  = *(const float4*)(aSeg  + (kb) + 4);                 \
        pb00 = *(const float4*)(bSeg0 + (kb));                     \
        pb01 = *(const float4*)(bSeg0 + (kb) + 4);                 \
        pb10 = *(const float4*)(bSeg1 + (kb));                     \
        pb11 = *(const float4*)(bSeg1 + (kb) + 4);                 \
    } while (0)

    float d[2][4][4] = {};

    V6_PREFETCH(0);

    for (int kt = 0; kt < 24; kt++) {
        const int buf = kt & 1;
        // stage prefetched regs -> smem, tf32-rounded, (c, c+4) interleave
        {
            float* ap = As + (buf * 64 + a_row) * V6_ST + a_ks * 8;
            float2 p;
            p.x = v6_tf32(pa0.x); p.y = v6_tf32(pa1.x); *(float2*)(ap + 0) = p;
            p.x = v6_tf32(pa0.y); p.y = v6_tf32(pa1.y); *(float2*)(ap + 2) = p;
            p.x = v6_tf32(pa0.z); p.y = v6_tf32(pa1.z); *(float2*)(ap + 4) = p;
            p.x = v6_tf32(pa0.w); p.y = v6_tf32(pa1.w); *(float2*)(ap + 6) = p;
            float* bp = Bs + (buf * 128 + b_row0) * V6_ST + b_ks0 * 8;
            p.x = v6_tf32(pb00.x); p.y = v6_tf32(pb01.x); *(float2*)(bp + 0) = p;
            p.x = v6_tf32(pb00.y); p.y = v6_tf32(pb01.y); *(float2*)(bp + 2) = p;
            p.x = v6_tf32(pb00.z); p.y = v6_tf32(pb01.z); *(float2*)(bp + 4) = p;
            p.x = v6_tf32(pb00.w); p.y = v6_tf32(pb01.w); *(float2*)(bp + 6) = p;
            bp = Bs + (buf * 128 + b_row1) * V6_ST + b_ks1 * 8;
            p.x = v6_tf32(pb10.x); p.y = v6_tf32(pb11.x); *(float2*)(bp + 0) = p;
            p.x = v6_tf32(pb10.y); p.y = v6_tf32(pb11.y); *(float2*)(bp + 2) = p;
            p.x = v6_tf32(pb10.z); p.y = v6_tf32(pb11.z); *(float2*)(bp + 4) = p;
            p.x = v6_tf32(pb10.w); p.y = v6_tf32(pb11.w); *(float2*)(bp + 6) = p;
        }
        __syncthreads();

        if (kt < 23) V6_PREFETCH((kt + 1) * 32);

        // compute 4 k-steps of 8
        const float* Ab = As + buf * 64 * V6_ST;
        const float* Bb = Bs + buf * 128 * V6_ST;
        #pragma unroll
        for (int s = 0; s < 4; s++) {
            unsigned afr[2][4];
            #pragma unroll
            for (int mf = 0; mf < 2; mf++) {
                const int r0 = warpM * 32 + mf * 16 + g;
                float2 p0 = *(const float2*)(Ab + r0 * V6_ST + s * 8 + t * 2);
                float2 p1 = *(const float2*)(Ab + (r0 + 8) * V6_ST + s * 8 + t * 2);
                afr[mf][0] = __float_as_uint(p0.x);
                afr[mf][1] = __float_as_uint(p1.x);
                afr[mf][2] = __float_as_uint(p0.y);
                afr[mf][3] = __float_as_uint(p1.y);
            }
            #pragma unroll
            for (int nf = 0; nf < 4; nf++) {
                const int n = warpN * 32 + nf * 8 + g;
                float2 q = *(const float2*)(Bb + n * V6_ST + s * 8 + t * 2);
                unsigned bfr[2] = { __float_as_uint(q.x), __float_as_uint(q.y) };
                v6_mma(d[0][nf], afr[0], bfr);
                v6_mma(d[1][nf], afr[1], bfr);
            }
        }
        __syncthreads();
    }

    // epilogue: direct stg (float2 per row pair), bias for query rows
    #pragma unroll
    for (int mf = 0; mf < 2; mf++) {
        const int r0 = warpM * 32 + mf * 16 + g;
        #pragma unroll
        for (int nf = 0; nf < 4; nf++) {
            const int c0 = jBase + warpN * 32 + nf * 8 + t * 2;
            float2 bias = make_float2(0.f, 0.f);
            if (isQ) bias = *(const float2*)(b1 + c0);
            float2 v0 = make_float2(d[mf][nf][0] + bias.x, d[mf][nf][1] + bias.y);
            float2 v1 = make_float2(d[mf][nf][2] + bias.x, d[mf][nf][3] + bias.y);
            *(float2*)(Crow + (size_t)r0 * TWO_D + c0)       = v0;
            *(float2*)(Crow + (size_t)(r0 + 8) * TWO_D + c0) = v1;
        }
    }
}

// ---------------------------------------------------------------------------
// Scores partial (fp64): part[z][q][s] = sum_{j in chunk z} relu(hq[q][j]+hs[s][j])*w2[j]
// (byte-identical logic to the PASSING R4 kernel)
// ---------------------------------------------------------------------------
__global__ void v6_scores(const float* __restrict__ W2)
{
    __shared__ __align__(16) float Aq[16][36];
    __shared__ __align__(16) float Bs[16][68];
    __shared__ float ws[16];

    const int tid    = threadIdx.x;
    const int sBase  = blockIdx.x * 64;
    const int qBase  = blockIdx.y * 32;
    const int jcBase = blockIdx.z * JPER;
    const int ty = tid >> 4;
    const int tx = tid & 15;

    const int aq_q = tid >> 3;
    const int aq_j = (tid & 7) * 2;
    const float* hqPtr = v6_hq + (size_t)(qBase + aq_q) * TWO_D + jcBase + aq_j;
    const int bs_s = tid >> 2;
    const int bs_j = (tid & 3) * 4;
    const float* hsPtr = v6_hs + (size_t)(sBase + bs_s) * TWO_D + jcBase + bs_j;

    double dacc[2][4] = {};

    for (int jt = 0; jt < JPER; jt += 16) {
        float2 a2 = *(const float2*)(hqPtr + jt);
        float4 b4 = *(const float4*)(hsPtr + jt);
        float wv = (tid < 16) ? W2[jcBase + jt + tid] : 0.0f;
        __syncthreads();
        Aq[aq_j+0][aq_q] = a2.x;
        Aq[aq_j+1][aq_q] = a2.y;
        Bs[bs_j+0][bs_s] = b4.x; Bs[bs_j+1][bs_s] = b4.y;
        Bs[bs_j+2][bs_s] = b4.z; Bs[bs_j+3][bs_s] = b4.w;
        if (tid < 16) ws[tid] = wv;
        __syncthreads();

        float p[2][4] = {};
        #pragma unroll
        for (int k = 0; k < 16; k++) {
            const float w  = ws[k];
            float2 aa = *(const float2*)&Aq[k][ty*2];
            float4 bb = *(const float4*)&Bs[k][tx*4];
            float a[2] = {aa.x, aa.y};
            float b[4] = {bb.x, bb.y, bb.z, bb.w};
            #pragma unroll
            for (int i = 0; i < 2; i++)
                #pragma unroll
                for (int l = 0; l < 4; l++) {
                    float tv = a[i] + b[l];
                    tv = fmaxf(tv, 0.0f);
                    p[i][l] = fmaf(tv, w, p[i][l]);
                }
        }
        #pragma unroll
        for (int i = 0; i < 2; i++)
            #pragma unroll
            for (int l = 0; l < 4; l++)
                dacc[i][l] += (double)p[i][l];
    }

    double* outp = v6_part + (size_t)blockIdx.z * (Q_N * S_N);
    #pragma unroll
    for (int i = 0; i < 2; i++)
        #pragma unroll
        for (int l = 0; l < 4; l++)
            outp[(size_t)(qBase + ty*2 + i) * S_N + sBase + tx*4 + l] = dacc[i][l];
}

// ---------------------------------------------------------------------------
// Per-query aggregate + softmax + pred (identical to passing R4)
// ---------------------------------------------------------------------------
__global__ void v6_agg(const int* __restrict__ labels,
                       const int* __restrict__ targets,
                       const float* __restrict__ b2,
                       float* __restrict__ out, int out_size)
{
    __shared__ double sc[S_N];
    __shared__ int    lab[S_N];
    __shared__ double aggv[C_N];
    __shared__ double redv[C_N];
    __shared__ int    redi[C_N];
    __shared__ double rede[C_N];

    const int q   = blockIdx.x;
    const int tid = threadIdx.x;
    const double b2v = (double)b2[0];

    for (int s = tid; s < S_N; s += 128) lab[s] = labels[s];

    for (int s = tid; s < S_N; s += 128) {
        double v = 0.0;
        #pragma unroll
        for (int z = 0; z < JCHUNKS; z++)
            v += v6_part[(size_t)z * (Q_N * S_N) + (size_t)q * S_N + s];
        sc[s] = v + b2v;
    }
    __syncthreads();

    if (tid < C_N) {
        double ssum = 0.0;
        int cnt = 0;
        for (int s = 0; s < S_N; s++)
            if (lab[s] == tid) { ssum += sc[s]; cnt++; }
        aggv[tid] = ssum / (double)(cnt > 1 ? cnt : 1);
        redv[tid] = aggv[tid];
        redi[tid] = tid;
    }
    __syncthreads();

    #pragma unroll
    for (int off = C_N / 2; off > 0; off >>= 1) {
        if (tid < off) {
            if (redv[tid + off] > redv[tid] ||
                (redv[tid + off] == redv[tid] && redi[tid + off] < redi[tid])) {
                redv[tid] = redv[tid + off];
                redi[tid] = redi[tid + off];
            }
        }
        __syncthreads();
    }
    const double mx = redv[0];
    const int    am = redi[0];

    if (tid < C_N) rede[tid] = exp(aggv[tid] - mx);
    __syncthreads();
    #pragma unroll
    for (int off = C_N / 2; off > 0; off >>= 1) {
        if (tid < off) rede[tid] += rede[tid + off];
        __syncthreads();
    }

    if (tid == 0) {
        const int tgt = targets[q];
        const double logp = aggv[tgt] - mx - log(rede[0]);
        v6_loss[q] = -logp;
        if (1 + q < out_size) out[1 + q] = (am == tgt) ? 1.0f : 0.0f;
    }
}

__global__ void v6_final(float* __restrict__ out, int out_size)
{
    __shared__ double red[Q_N];
    const int tid = threadIdx.x;
    red[tid] = v6_loss[tid];
    __syncthreads();
    #pragma unroll
    for (int off = Q_N / 2; off > 0; off >>= 1) {
        if (tid < off) red[tid] += red[tid + off];
        __syncthreads();
    }
    if (tid == 0 && out_size > 0) out[0] = (float)(red[0] / (double)Q_N);
}

// ---------------------------------------------------------------------------
extern "C" void kernel_launch(void* const* d_in, const int* in_sizes, int n_in,
                              void* d_out, int out_size)
{
    const float* query   = (const float*)d_in[0];   // [128,768]
    const float* support = (const float*)d_in[1];   // [512,768]
    const float* W1      = (const float*)d_in[2];   // [1536,1536]
    const float* b1      = (const float*)d_in[3];   // [1536]
    const float* W2      = (const float*)d_in[4];   // [1,1536]
    const float* b2      = (const float*)d_in[5];   // [1]
    const int*   labels  = (const int*)  d_in[6];   // [512] sorted
    const int*   targets = (const int*)  d_in[7];   // [128]
    (void)in_sizes; (void)n_in;

    float* out = (float*)d_out;

    cudaFuncSetAttribute(v6_gemm, cudaFuncAttributeMaxDynamicSharedMemorySize, V6_SMEM);

    v6_gemm  <<<dim3(TWO_D/128, 10), 256, V6_SMEM>>>(query, support, W1, b1);
    v6_scores<<<dim3(S_N/64, Q_N/32, JCHUNKS), 256>>>(W2);
    v6_agg   <<<Q_N, 128>>>(labels, targets, b2, out, out_size);
    v6_final <<<1, Q_N>>>(out, out_size);
}

// round 7
// speedup vs baseline: 2.2456x; 1.2212x over previous
#include <cuda_runtime.h>
#include <math.h>
#include <stdint.h>

#define D_IN   768
#define TWO_D  1536
#define Q_N    128
#define S_N    512
#define C_N    64
#define JCHUNKS 8
#define JPER   (TWO_D / JCHUNKS)    /* 192 */

typedef unsigned long long ull;

// Scratch (device globals: allocation-free per harness rules)
__device__ float    v7_hq[Q_N * TWO_D];             // hq (+b1)  [128,1536]
__device__ float    v7_hs[S_N * TWO_D];             // hs        [512,1536]
__device__ double   v7_part[JCHUNKS * Q_N * S_N];   // fp64 partial scores per j-chunk
__device__ double   v7_loss[Q_N];                   // per-query -logp
__device__ unsigned v7_ticket = 0;                  // last-block ticket for merged final

// fp32 -> tf32 RNA rounding (matches cuBLAS TF32 input quantization = reference)
__device__ __forceinline__ float v7_tf32(float x) {
    unsigned u;
    asm("cvt.rna.tf32.f32 %0, %1;" : "=r"(u) : "f"(x));
    return __uint_as_float(u);
}

// m16n8k8 tf32 mma (base ISA, sm_80+)
__device__ __forceinline__ void v7_mma(float d[4], const unsigned a[4], const unsigned b[2]) {
    asm volatile(
        "mma.sync.aligned.m16n8k8.row.col.f32.tf32.tf32.f32 "
        "{%0,%1,%2,%3}, {%4,%5,%6,%7}, {%8,%9}, {%0,%1,%2,%3};"
        : "+f"(d[0]), "+f"(d[1]), "+f"(d[2]), "+f"(d[3])
        : "r"(a[0]), "r"(a[1]), "r"(a[2]), "r"(a[3]), "r"(b[0]), "r"(b[1]));
}

// packed f32x2 (base ISA on sm_100+ family; SASS FADD2/FFMA2)
#define V7_ADD2(d, a, b) \
    asm("add.rn.f32x2 %0, %1, %2;" : "=l"(d) : "l"(a), "l"(b))
#define V7_FMA2(acc, t, w) \
    asm("fma.rn.f32x2 %0, %1, %2, %0;" : "+l"(acc) : "l"(t), "l"(w))

// packed relu: per 32-bit lane, as_float(max(as_int(x),0)) == relu(x) for non-NaN.
// IMAX runs on the ALU pipe, off the critical fma pipe. mov.b64 pack/unpack is free.
__device__ __forceinline__ ull v7_relu2(ull t) {
    unsigned lo, hi;
    asm("mov.b64 {%0,%1}, %2;" : "=r"(lo), "=r"(hi) : "l"(t));
    int l2 = max((int)lo, 0);
    int h2 = max((int)hi, 0);
    ull r;
    asm("mov.b64 %0, {%1,%2};" : "=l"(r) : "r"((unsigned)l2), "r"((unsigned)h2));
    return r;
}

// ---------------------------------------------------------------------------
// TF32 tensor-core GEMM (identical to passing R6): h = tf32(A) @ tf32(W1).T
// CTA 64m x 128n, 24 double-buffered k-tiles of 32; 8 warps (2M x 4N).
// grid = (12, 10)
// ---------------------------------------------------------------------------
#define V7_ST     40
#define V7_ASZ    (2 * 64 * V7_ST)
#define V7_BSZ    (2 * 128 * V7_ST)
#define V7_SMEM   ((V7_ASZ + V7_BSZ) * 4)

__global__ void __launch_bounds__(256, 1)
v7_gemm(const float* __restrict__ query,
        const float* __restrict__ support,
        const float* __restrict__ W1,
        const float* __restrict__ b1)
{
    extern __shared__ __align__(16) float smem[];
    float* As = smem;              // [2][64][40]
    float* Bs = smem + V7_ASZ;     // [2][128][40]

    const int tid  = threadIdx.x;
    const int lane = tid & 31;
    const int wid  = tid >> 5;
    const int warpM = wid & 1;
    const int warpN = wid >> 1;
    const int g = lane >> 2;
    const int t = lane & 3;

    const bool isQ  = (blockIdx.y < 2);
    const float* Arow = isQ ? (query + (size_t)blockIdx.y * 64 * D_IN)
                            : (support + (size_t)(blockIdx.y - 2) * 64 * D_IN);
    const int   wOff  = isQ ? 0 : D_IN;
    const int   jBase = blockIdx.x * 128;
    float* Crow = isQ ? (v7_hq + (size_t)blockIdx.y * 64 * TWO_D)
                      : (v7_hs + (size_t)(blockIdx.y - 2) * 64 * TWO_D);

    const int a_row = tid >> 2, a_ks = tid & 3;
    const int b_row0 = tid >> 2, b_ks0 = tid & 3;
    const int b_row1 = (tid + 256) >> 2, b_ks1 = tid & 3;
    const float* aSeg  = Arow + (size_t)a_row * D_IN + a_ks * 8;
    const float* bSeg0 = W1 + (size_t)(jBase + b_row0) * TWO_D + wOff + b_ks0 * 8;
    const float* bSeg1 = W1 + (size_t)(jBase + b_row1) * TWO_D + wOff + b_ks1 * 8;

    float4 pa0, pa1, pb00, pb01, pb10, pb11;
    #define V7_PREFETCH(kb) do {                                   \
        pa0  = *(const float4*)(aSeg  + (kb));                     \
        pa1  = *(const float4*)(aSeg  + (kb) + 4);                 \
        pb00 = *(const float4*)(bSeg0 + (kb));                     \
        pb01 = *(const float4*)(bSeg0 + (kb) + 4);                 \
        pb10 = *(const float4*)(bSeg1 + (kb));                     \
        pb11 = *(const float4*)(bSeg1 + (kb) + 4);                 \
    } while (0)

    float d[2][4][4] = {};

    V7_PREFETCH(0);

    for (int kt = 0; kt < 24; kt++) {
        const int buf = kt & 1;
        {
            float* ap = As + (buf * 64 + a_row) * V7_ST + a_ks * 8;
            float2 p;
            p.x = v7_tf32(pa0.x); p.y = v7_tf32(pa1.x); *(float2*)(ap + 0) = p;
            p.x = v7_tf32(pa0.y); p.y = v7_tf32(pa1.y); *(float2*)(ap + 2) = p;
            p.x = v7_tf32(pa0.z); p.y = v7_tf32(pa1.z); *(float2*)(ap + 4) = p;
            p.x = v7_tf32(pa0.w); p.y = v7_tf32(pa1.w); *(float2*)(ap + 6) = p;
            float* bp = Bs + (buf * 128 + b_row0) * V7_ST + b_ks0 * 8;
            p.x = v7_tf32(pb00.x); p.y = v7_tf32(pb01.x); *(float2*)(bp + 0) = p;
            p.x = v7_tf32(pb00.y); p.y = v7_tf32(pb01.y); *(float2*)(bp + 2) = p;
            p.x = v7_tf32(pb00.z); p.y = v7_tf32(pb01.z); *(float2*)(bp + 4) = p;
            p.x = v7_tf32(pb00.w); p.y = v7_tf32(pb01.w); *(float2*)(bp + 6) = p;
            bp = Bs + (buf * 128 + b_row1) * V7_ST + b_ks1 * 8;
            p.x = v7_tf32(pb10.x); p.y = v7_tf32(pb11.x); *(float2*)(bp + 0) = p;
            p.x = v7_tf32(pb10.y); p.y = v7_tf32(pb11.y); *(float2*)(bp + 2) = p;
            p.x = v7_tf32(pb10.z); p.y = v7_tf32(pb11.z); *(float2*)(bp + 4) = p;
            p.x = v7_tf32(pb10.w); p.y = v7_tf32(pb11.w); *(float2*)(bp + 6) = p;
        }
        __syncthreads();

        if (kt < 23) V7_PREFETCH((kt + 1) * 32);

        const float* Ab = As + buf * 64 * V7_ST;
        const float* Bb = Bs + buf * 128 * V7_ST;
        #pragma unroll
        for (int s = 0; s < 4; s++) {
            unsigned afr[2][4];
            #pragma unroll
            for (int mf = 0; mf < 2; mf++) {
                const int r0 = warpM * 32 + mf * 16 + g;
                float2 p0 = *(const float2*)(Ab + r0 * V7_ST + s * 8 + t * 2);
                float2 p1 = *(const float2*)(Ab + (r0 + 8) * V7_ST + s * 8 + t * 2);
                afr[mf][0] = __float_as_uint(p0.x);
                afr[mf][1] = __float_as_uint(p1.x);
                afr[mf][2] = __float_as_uint(p0.y);
                afr[mf][3] = __float_as_uint(p1.y);
            }
            #pragma unroll
            for (int nf = 0; nf < 4; nf++) {
                const int n = warpN * 32 + nf * 8 + g;
                float2 q = *(const float2*)(Bb + n * V7_ST + s * 8 + t * 2);
                unsigned bfr[2] = { __float_as_uint(q.x), __float_as_uint(q.y) };
                v7_mma(d[0][nf], afr[0], bfr);
                v7_mma(d[1][nf], afr[1], bfr);
            }
        }
        __syncthreads();
    }

    #pragma unroll
    for (int mf = 0; mf < 2; mf++) {
        const int r0 = warpM * 32 + mf * 16 + g;
        #pragma unroll
        for (int nf = 0; nf < 4; nf++) {
            const int c0 = jBase + warpN * 32 + nf * 8 + t * 2;
            float2 bias = make_float2(0.f, 0.f);
            if (isQ) bias = *(const float2*)(b1 + c0);
            float2 v0 = make_float2(d[mf][nf][0] + bias.x, d[mf][nf][1] + bias.y);
            float2 v1 = make_float2(d[mf][nf][2] + bias.x, d[mf][nf][3] + bias.y);
            *(float2*)(Crow + (size_t)r0 * TWO_D + c0)       = v0;
            *(float2*)(Crow + (size_t)(r0 + 8) * TWO_D + c0) = v1;
        }
    }
}

// ---------------------------------------------------------------------------
// Scores partial, packed f32x2 + ALU-pipe relu:
//   part[z][q][s] = sum_{j in chunk z} relu(hq[q][j]+hs[s][j]) * w2[j]
// j processed as pairs (even in .lo, odd in .hi). Per thread: 2 q x 4 s,
// s strided (tx + l*16) for conflict-free LDS64. fp32 pair-accumulate,
// fp64 flush every 64 j. grid = (8, 4, JCHUNKS=8), 256 threads.
// ---------------------------------------------------------------------------
__global__ void v7_scores(const float* __restrict__ W2)
{
    __shared__ __align__(16) float2 Aq2[8][34];   // padded: conflict-free STS
    __shared__ __align__(16) float2 Bs2[8][66];   // padded: conflict-free STS
    __shared__ float2 ws2[8];

    const int tid    = threadIdx.x;
    const int sBase  = blockIdx.x * 64;
    const int qBase  = blockIdx.y * 32;
    const int jcBase = blockIdx.z * JPER;
    const int ty = tid >> 4;      // 0..15 -> q rows ty*2, ty*2+1
    const int tx = tid & 15;      // 0..15 -> s cols tx + l*16

    const int aq_q  = tid >> 3;          // 0..31
    const int aq_jp = tid & 7;           // j-pair slot
    const float* hqPtr = v7_hq + (size_t)(qBase + aq_q) * TWO_D + jcBase + aq_jp * 2;
    const int bs_s  = tid >> 2;          // 0..63
    const int bs_jp = (tid & 3) * 2;     // 2 j-pair slots
    const float* hsPtr = v7_hs + (size_t)(sBase + bs_s) * TWO_D + jcBase + bs_jp * 2;

    double dacc[2][4] = {};
    ull acc2[2][4] = {};                 // f32x2 accumulators (bits 0 == (+0,+0))

    for (int jt = 0; jt < JPER; jt += 16) {
        float2 aval = *(const float2*)(hqPtr + jt);
        float4 bval = *(const float4*)(hsPtr + jt);
        float2 wval = make_float2(0.f, 0.f);
        if (tid < 8) wval = *(const float2*)(W2 + jcBase + jt + tid * 2);
        __syncthreads();
        Aq2[aq_jp][aq_q] = aval;
        Bs2[bs_jp][bs_s]     = make_float2(bval.x, bval.y);
        Bs2[bs_jp + 1][bs_s] = make_float2(bval.z, bval.w);
        if (tid < 8) ws2[tid] = wval;
        __syncthreads();

        #pragma unroll
        for (int jp = 0; jp < 8; jp++) {
            const ull w2v = *(const ull*)&ws2[jp];
            const ull a0  = *(const ull*)&Aq2[jp][ty * 2];
            const ull a1  = *(const ull*)&Aq2[jp][ty * 2 + 1];
            #pragma unroll
            for (int l = 0; l < 4; l++) {
                const ull bv = *(const ull*)&Bs2[jp][tx + l * 16];
                ull t0; V7_ADD2(t0, a0, bv);
                t0 = v7_relu2(t0);
                V7_FMA2(acc2[0][l], t0, w2v);
                ull t1; V7_ADD2(t1, a1, bv);
                t1 = v7_relu2(t1);
                V7_FMA2(acc2[1][l], t1, w2v);
            }
        }

        if ((jt & 63) == 48) {   // flush at 64/128/192-j boundaries
            #pragma unroll
            for (int i = 0; i < 2; i++)
                #pragma unroll
                for (int l = 0; l < 4; l++) {
                    unsigned lo, hi;
                    asm("mov.b64 {%0,%1}, %2;" : "=r"(lo), "=r"(hi) : "l"(acc2[i][l]));
                    dacc[i][l] += (double)(__uint_as_float(lo) + __uint_as_float(hi));
                    acc2[i][l] = 0ull;
                }
        }
    }

    double* outp = v7_part + (size_t)blockIdx.z * (Q_N * S_N);
    #pragma unroll
    for (int i = 0; i < 2; i++)
        #pragma unroll
        for (int l = 0; l < 4; l++)
            outp[(size_t)(qBase + ty * 2 + i) * S_N + sBase + tx + l * 16] = dacc[i][l];
}

// ---------------------------------------------------------------------------
// Per-query aggregate + softmax + pred, with merged final loss reduction:
// the last block to finish (ticket) reduces v7_loss in fixed order -> out[0].
// grid = 128 blocks (1/query), 128 threads. All fp64, deterministic.
// ---------------------------------------------------------------------------
__global__ void v7_agg(const int* __restrict__ labels,
                       const int* __restrict__ targets,
                       const float* __restrict__ b2,
                       float* __restrict__ out, int out_size)
{
    __shared__ double sc[S_N];
    __shared__ int    lab[S_N];
    __shared__ double aggv[C_N];
    __shared__ double redv[C_N];
    __shared__ int    redi[C_N];
    __shared__ double rede[C_N];
    __shared__ int    isLast;
    __shared__ double lred[Q_N];

    const int q   = blockIdx.x;
    const int tid = threadIdx.x;
    const double b2v = (double)b2[0];

    for (int s = tid; s < S_N; s += 128) lab[s] = labels[s];

    for (int s = tid; s < S_N; s += 128) {
        double v = 0.0;
        #pragma unroll
        for (int z = 0; z < JCHUNKS; z++)
            v += v7_part[(size_t)z * (Q_N * S_N) + (size_t)q * S_N + s];
        sc[s] = v + b2v;
    }
    __syncthreads();

    if (tid < C_N) {
        double ssum = 0.0;
        int cnt = 0;
        for (int s = 0; s < S_N; s++)
            if (lab[s] == tid) { ssum += sc[s]; cnt++; }
        aggv[tid] = ssum / (double)(cnt > 1 ? cnt : 1);
        redv[tid] = aggv[tid];
        redi[tid] = tid;
    }
    __syncthreads();

    #pragma unroll
    for (int off = C_N / 2; off > 0; off >>= 1) {
        if (tid < off) {
            if (redv[tid + off] > redv[tid] ||
                (redv[tid + off] == redv[tid] && redi[tid + off] < redi[tid])) {
                redv[tid] = redv[tid + off];
                redi[tid] = redi[tid + off];
            }
        }
        __syncthreads();
    }
    const double mx = redv[0];
    const int    am = redi[0];

    if (tid < C_N) rede[tid] = exp(aggv[tid] - mx);
    __syncthreads();
    #pragma unroll
    for (int off = C_N / 2; off > 0; off >>= 1) {
        if (tid < off) rede[tid] += rede[tid + off];
        __syncthreads();
    }

    if (tid == 0) {
        const int tgt = targets[q];
        const double logp = aggv[tgt] - mx - log(rede[0]);
        v7_loss[q] = -logp;
        if (1 + q < out_size) out[1 + q] = (am == tgt) ? 1.0f : 0.0f;
        __threadfence();
        unsigned tk = atomicAdd(&v7_ticket, 1u);
        isLast = (tk == (unsigned)(Q_N - 1));
    }
    __syncthreads();

    if (isLast) {
        __threadfence();                   // acquire: all v7_loss writes visible
        lred[tid] = v7_loss[tid];
        __syncthreads();
        #pragma unroll
        for (int off = Q_N / 2; off > 0; off >>= 1) {
            if (tid < off) lred[tid] += lred[tid + off];
            __syncthreads();
        }
        if (tid == 0) {
            if (out_size > 0) out[0] = (float)(lred[0] / (double)Q_N);
            v7_ticket = 0;                 // reset for next graph replay
        }
    }
}

// ---------------------------------------------------------------------------
extern "C" void kernel_launch(void* const* d_in, const int* in_sizes, int n_in,
                              void* d_out, int out_size)
{
    const float* query   = (const float*)d_in[0];   // [128,768]
    const float* support = (const float*)d_in[1];   // [512,768]
    const float* W1      = (const float*)d_in[2];   // [1536,1536]
    const float* b1      = (const float*)d_in[3];   // [1536]
    const float* W2      = (const float*)d_in[4];   // [1,1536]
    const float* b2      = (const float*)d_in[5];   // [1]
    const int*   labels  = (const int*)  d_in[6];   // [512] sorted
    const int*   targets = (const int*)  d_in[7];   // [128]
    (void)in_sizes; (void)n_in;

    float* out = (float*)d_out;

    cudaFuncSetAttribute(v7_gemm, cudaFuncAttributeMaxDynamicSharedMemorySize, V7_SMEM);

    v7_gemm  <<<dim3(TWO_D/128, 10), 256, V7_SMEM>>>(query, support, W1, b1);
    v7_scores<<<dim3(S_N/64, Q_N/32, JCHUNKS), 256>>>(W2);
    v7_agg   <<<Q_N, 128>>>(labels, targets, b2, out, out_size);
}